// round 6
// baseline (speedup 1.0000x reference)
#include <cuda_runtime.h>

// MaskedLoss: loss = sum_b sum_{unique (r,c)} (y_true[b,r,c] - y_pred[b,r,c])^2
// B=64, N=1000, K=128. Sparse gather (~8K of 64M positions).
// One fused kernel, 64 blocks (one per batch). Critical path minimized to
// two serial DRAM epochs: [index load] -> [gather], then a scoped-atomic tail.

#define MB_B   64
#define MB_K   128
#define MB_N   1000

// Allocation-free scratch. Zero at module load; the last block restores both
// to 0 every launch, so every graph replay sees identical state.
__device__ float        g_accum;
__device__ unsigned int g_count;

__global__ __launch_bounds__(MB_K)
void masked_loss_fused_kernel(const float* __restrict__ y_true,
                              const float* __restrict__ y_pred,
                              const unsigned int* __restrict__ rows_w,
                              const unsigned int* __restrict__ cols_w,
                              float* __restrict__ out)
{
    const int k = threadIdx.x;   // 0..127 : index-pair id
    const int b = blockIdx.x;    // 0..63  : batch row

    __shared__ unsigned int s_rows[128];   // words 0..127 of rows (first 512B)
    __shared__ unsigned int s_cols[128];
    __shared__ int          s_tab[256];    // dedup hash table
    __shared__ float        s_red[MB_K / 32];
    __shared__ int          s_flag;        // 1 = int32 indices, 0 = int64

    s_tab[k]       = -1;
    s_tab[k + 128] = -1;

    // ---- epoch 1: one coalesced load of the first 512B of each index array.
    // uint2 at [k] = 32-bit words 2k,2k+1. In the int64 case that pair IS
    // element k (lo,hi) — threads 0..63 already hold their element.
    uint2 r2 = make_uint2(0u, 0u), c2 = make_uint2(0u, 0u);
    if (k < 64) {
        r2 = ((const uint2*)rows_w)[k];
        c2 = ((const uint2*)cols_w)[k];
        s_rows[2 * k]     = r2.x;  s_rows[2 * k + 1] = r2.y;
        s_cols[2 * k]     = c2.x;  s_cols[2 * k + 1] = c2.y;
        if (k < 32) {
            // Width verdict: int64 (values<1000) -> hi-words all zero.
            // int32 -> 32 random indices in [0,1000); all-zero prob ~1e-96.
            unsigned int bal = __ballot_sync(0xffffffffu, r2.y != 0u);
            if (k == 0) s_flag = (bal != 0u);
        }
    } else if (k < 68) {
        // Non-faulting L2 prefetch of bytes [512,1024) (int64 upper half),
        // concurrent with epoch 1. Hint only — safe for either width.
        const char* p = (const char*)rows_w + 512 + (k - 64) * 128;
        asm volatile("prefetch.global.L2 [%0];" :: "l"(p));
    } else if (k >= 96 && k < 100) {
        const char* p = (const char*)cols_w + 512 + (k - 96) * 128;
        asm volatile("prefetch.global.L2 [%0];" :: "l"(p));
    }
    __syncthreads();   // s_tab init + staged words + s_flag visible

    int r, c;
    if (s_flag) {                // int32: word k, staged by thread k/2
        r = (int)s_rows[k];
        c = (int)s_cols[k];
    } else {                     // int64: element k = words 2k,2k+1
        if (k >= 64) {           // in-bounds: buffer is 1024B; L2-prefetched
            r2 = ((const uint2*)rows_w)[k];
            c2 = ((const uint2*)cols_w)[k];
        }
        r = (int)r2.x;
        c = (int)c2.x;
    }
    const int my = r * MB_N + c;

    // ---- dedup via shared-mem hash (any single winner per value is correct;
    //      duplicates address the same element) -----------------------------
    unsigned int h = ((unsigned int)my * 2654435761u) >> 24;  // 0..255
    bool uniq = false;
    for (;;) {
        int prev = atomicCAS(&s_tab[h], -1, my);
        if (prev == -1) { uniq = true; break; }
        if (prev == my) break;
        h = (h + 1) & 255;
    }

    // ---- epoch 2: gather + squared diff (offset < 2^31) --------------------
    float v = 0.0f;
    if (uniq) {
        const int off = b * (MB_N * MB_N) + my;
        const float d = __ldg(y_true + off) - __ldg(y_pred + off);
        v = d * d;
    }

    // ---- block reduce (4 warps) ---------------------------------------------
    #pragma unroll
    for (int o = 16; o > 0; o >>= 1)
        v += __shfl_down_sync(0xffffffffu, v, o);
    if ((k & 31) == 0) s_red[k >> 5] = v;
    __syncthreads();

    // ---- cross-block tail: scoped atomics, no membar.gl / L1 flush ----------
    if (k == 0) {
        const float bs = s_red[0] + s_red[1] + s_red[2] + s_red[3];

        asm volatile("red.relaxed.gpu.global.add.f32 [%0], %1;"
                     :: "l"(&g_accum), "f"(bs) : "memory");

        unsigned int t;
        asm volatile("atom.release.gpu.global.add.u32 %0, [%1], %2;"
                     : "=r"(t) : "l"(&g_count), "r"(1u) : "memory");

        if (t == MB_B - 1) {     // last block: all 64 partials are at L2
            float total; float zero = 0.0f;
            asm volatile("atom.acquire.gpu.global.exch.b32 %0, [%1], %2;"
                         : "=f"(total) : "l"(&g_accum), "f"(zero) : "memory");
            g_count = 0;         // reset for the next graph replay
            out[0] = total;
        }
    }
}

// ---------------------------------------------------------------------------
// Launch contract
//   d_in[0] = y_true  (float32, B*N*N)
//   d_in[1] = y_pred  (float32, B*N*N)
//   d_in[2] = rows    (int64 or int32, K)
//   d_in[3] = cols    (int64 or int32, K)
//   d_out   = float32 scalar
// ---------------------------------------------------------------------------
extern "C" void kernel_launch(void* const* d_in, const int* in_sizes, int n_in,
                              void* d_out, int out_size)
{
    const float*        y_true = (const float*)d_in[0];
    const float*        y_pred = (const float*)d_in[1];
    const unsigned int* rows_w = (const unsigned int*)d_in[2];
    const unsigned int* cols_w = (const unsigned int*)d_in[3];
    float*              out    = (float*)d_out;

    masked_loss_fused_kernel<<<MB_B, MB_K>>>(y_true, y_pred, rows_w, cols_w, out);
}

// round 7
// speedup vs baseline: 1.0295x; 1.0295x over previous
#include <cuda_runtime.h>

// MaskedLoss: loss = sum_b sum_{unique (r,c)} (y_true[b,r,c] - y_pred[b,r,c])^2
// B=64, N=1000, K=128. Sparse gather (~8K of 64M positions).
// One fused kernel, 64 blocks (one per batch). Critical path: two serial DRAM
// epochs [index load -> gather], then a per-warp scoped-atomic tail (no second
// __syncthreads, no shared reduce stage, no membar.gl).

#define MB_B   64
#define MB_K   128
#define MB_N   1000
#define MB_WARPS_TOTAL (MB_B * (MB_K / 32))   // 256 warp-level arrivals

// Allocation-free scratch. Zero at module load; the last warp restores both
// to 0 every launch, so every graph replay sees identical state.
__device__ float        g_accum;
__device__ unsigned int g_count;

__global__ __launch_bounds__(MB_K)
void masked_loss_fused_kernel(const float* __restrict__ y_true,
                              const float* __restrict__ y_pred,
                              const unsigned int* __restrict__ rows_w,
                              const unsigned int* __restrict__ cols_w,
                              float* __restrict__ out)
{
    const int k = threadIdx.x;   // 0..127 : index-pair id
    const int b = blockIdx.x;    // 0..63  : batch row

    __shared__ unsigned int s_rows[128];   // words 0..127 of rows (first 512B)
    __shared__ unsigned int s_cols[128];
    __shared__ int          s_tab[256];    // dedup hash table
    __shared__ int          s_flag;        // 1 = int32 indices, 0 = int64

    s_tab[k]       = -1;
    s_tab[k + 128] = -1;

    // ---- epoch 1: one coalesced load of the first 512B of each index array.
    // uint2 at [k] = 32-bit words 2k,2k+1. In the int64 case that pair IS
    // element k (lo,hi) — threads 0..63 already hold their element.
    uint2 r2 = make_uint2(0u, 0u), c2 = make_uint2(0u, 0u);
    if (k < 64) {
        r2 = ((const uint2*)rows_w)[k];
        c2 = ((const uint2*)cols_w)[k];
        s_rows[2 * k]     = r2.x;  s_rows[2 * k + 1] = r2.y;
        s_cols[2 * k]     = c2.x;  s_cols[2 * k + 1] = c2.y;
        if (k < 32) {
            // Width verdict: int64 (values<1000) -> hi-words all zero.
            // int32 -> 32 random indices in [0,1000); all-zero prob ~1e-96.
            unsigned int bal = __ballot_sync(0xffffffffu, r2.y != 0u);
            if (k == 0) s_flag = (bal != 0u);
        }
    } else if (k < 68) {
        // Non-faulting L2 prefetch of bytes [512,1024) (int64 upper half),
        // concurrent with epoch 1. Hint only — safe for either width.
        const char* p = (const char*)rows_w + 512 + (k - 64) * 128;
        asm volatile("prefetch.global.L2 [%0];" :: "l"(p));
    } else if (k >= 96 && k < 100) {
        const char* p = (const char*)cols_w + 512 + (k - 96) * 128;
        asm volatile("prefetch.global.L2 [%0];" :: "l"(p));
    }
    __syncthreads();   // s_tab init + staged words + s_flag visible

    int r, c;
    if (s_flag) {                // int32: word k, staged by thread k/2
        r = (int)s_rows[k];
        c = (int)s_cols[k];
    } else {                     // int64: element k = words 2k,2k+1
        if (k >= 64) {           // in-bounds: buffer is 1024B; L2-prefetched
            r2 = ((const uint2*)rows_w)[k];
            c2 = ((const uint2*)cols_w)[k];
        }
        r = (int)r2.x;
        c = (int)c2.x;
    }
    const int my = r * MB_N + c;

    // ---- dedup via shared-mem hash (any single winner per value is correct;
    //      duplicates address the same element) -----------------------------
    unsigned int h = ((unsigned int)my * 2654435761u) >> 24;  // 0..255
    bool uniq = false;
    for (;;) {
        int prev = atomicCAS(&s_tab[h], -1, my);
        if (prev == -1) { uniq = true; break; }
        if (prev == my) break;
        h = (h + 1) & 255;
    }

    // ---- epoch 2: gather + squared diff (offset < 2^31) --------------------
    float v = 0.0f;
    if (uniq) {
        const int off = b * (MB_N * MB_N) + my;
        const float d = __ldg(y_true + off) - __ldg(y_pred + off);
        v = d * d;
    }

    // ---- warp reduce --------------------------------------------------------
    #pragma unroll
    for (int o = 16; o > 0; o >>= 1)
        v += __shfl_down_sync(0xffffffffu, v, o);

    // ---- per-warp tail: 256 warp-level arrivals chip-wide, no block barrier --
    if ((k & 31) == 0) {
        // relaxed accumulate of this warp's partial (L2 atomic, ~0.85cyc/op)
        asm volatile("red.relaxed.gpu.global.add.f32 [%0], %1;"
                     :: "l"(&g_accum), "f"(v) : "memory");

        // acq_rel ticket: releases my add; the 256th arrival acquires all 255
        // prior releases, making every accumulate visible to it.
        unsigned int t;
        asm volatile("atom.acq_rel.gpu.global.add.u32 %0, [%1], %2;"
                     : "=r"(t) : "l"(&g_count), "r"(1u) : "memory");

        if (t == MB_WARPS_TOTAL - 1) {   // last warp chip-wide
            float total; float zero = 0.0f;
            asm volatile("atom.acquire.gpu.global.exch.b32 %0, [%1], %2;"
                         : "=f"(total) : "l"(&g_accum), "f"(zero) : "memory");
            g_count = 0;                 // reset for the next graph replay
            out[0] = total;
        }
    }
}

// ---------------------------------------------------------------------------
// Launch contract
//   d_in[0] = y_true  (float32, B*N*N)
//   d_in[1] = y_pred  (float32, B*N*N)
//   d_in[2] = rows    (int64 or int32, K)
//   d_in[3] = cols    (int64 or int32, K)
//   d_out   = float32 scalar
// ---------------------------------------------------------------------------
extern "C" void kernel_launch(void* const* d_in, const int* in_sizes, int n_in,
                              void* d_out, int out_size)
{
    const float*        y_true = (const float*)d_in[0];
    const float*        y_pred = (const float*)d_in[1];
    const unsigned int* rows_w = (const unsigned int*)d_in[2];
    const unsigned int* cols_w = (const unsigned int*)d_in[3];
    float*              out    = (float*)d_out;

    masked_loss_fused_kernel<<<MB_B, MB_K>>>(y_true, y_pred, rows_w, cols_w, out);
}

// round 8
// speedup vs baseline: 1.3413x; 1.3029x over previous
#include <cuda_runtime.h>

// MaskedLoss: loss = sum_b sum_{unique (r,c)} (y_true[b,r,c] - y_pred[b,r,c])^2
// B=64, N=1000, K=128. Sparse gather (~8K of 64M positions).
// One fused kernel, 64 blocks (one per batch). Critical path: two serial
// memory epochs [index load -> gather] with the dedup hash hidden under the
// gather, then a SINGLE packed u64 atomic per warp as the entire cross-block
// reduction + ticket + acquire (returned pre-value carries all prior sums).

#define MB_B   64
#define MB_K   128
#define MB_N   1000
#define MB_WARPS_TOTAL (MB_B * (MB_K / 32))   // 256 warp-level arrivals

// Packed accumulator: bits [56,64) = arrival count, bits [0,56) = fixed-point
// sum (scale 2^30; total < 2^26 so no carry into the count field).
// Zero at module load; the last warp resets it every launch -> every graph
// replay sees identical state.
__device__ unsigned long long g_pack;

__global__ __launch_bounds__(MB_K)
void masked_loss_fused_kernel(const float* __restrict__ y_true,
                              const float* __restrict__ y_pred,
                              const unsigned int* __restrict__ rows_w,
                              const unsigned int* __restrict__ cols_w,
                              float* __restrict__ out)
{
    const int k = threadIdx.x;   // 0..127 : index-pair id
    const int b = blockIdx.x;    // 0..63  : batch row

    __shared__ int s_tab[256];   // dedup hash table
    __shared__ int s_flag;       // 1 = int32 indices, 0 = int64

    s_tab[k]       = -1;
    s_tab[k + 128] = -1;

    // ---- epoch 1: one coalesced load of the first 512B of each index array.
    // uint2 at [k] = 32-bit words 2k,2k+1. In the int64 case that pair IS
    // element k (lo,hi) — threads 0..63 already hold their element.
    uint2 r2 = make_uint2(0u, 0u), c2 = make_uint2(0u, 0u);
    if (k < 64) {
        r2 = ((const uint2*)rows_w)[k];
        c2 = ((const uint2*)cols_w)[k];
        if (k < 32) {
            // Width verdict: int64 (values<1000) -> hi-words all zero.
            // int32 -> 32 random indices in [0,1000); all-zero prob ~1e-96.
            unsigned int bal = __ballot_sync(0xffffffffu, r2.y != 0u);
            if (k == 0) s_flag = (bal != 0u);
        }
    } else if (k < 68) {
        // Non-faulting L2 prefetch of bytes [512,1024) (int64 upper half),
        // concurrent with epoch 1. Hint only — safe for either width.
        const char* p = (const char*)rows_w + 512 + (k - 64) * 128;
        asm volatile("prefetch.global.L2 [%0];" :: "l"(p));
    } else if (k >= 96 && k < 100) {
        const char* p = (const char*)cols_w + 512 + (k - 96) * 128;
        asm volatile("prefetch.global.L2 [%0];" :: "l"(p));
    }
    __syncthreads();   // s_tab init + s_flag visible

    int r, c;
    if (s_flag) {                // int32: word k — L1 hit (lines fetched above)
        r = (int)__ldg(rows_w + k);
        c = (int)__ldg(cols_w + k);
    } else {                     // int64: element k = words 2k,2k+1
        if (k >= 64) {           // in-bounds: buffer is 1024B; L2-prefetched
            r2 = ((const uint2*)rows_w)[k];
            c2 = ((const uint2*)cols_w)[k];
        }
        r = (int)r2.x;
        c = (int)c2.x;
    }
    const int my = r * MB_N + c;

    // ---- epoch 2: issue gathers IMMEDIATELY (independent of dedup; duplicate
    //      threads load the same address — L2 dedups). Offset < 2^31.
    const int off = b * (MB_N * MB_N) + my;
    const float yt = __ldg(y_true + off);
    const float yp = __ldg(y_pred + off);

    // ---- dedup via shared-mem hash, hidden under the gather latency.
    //      Any single winner per value is correct (duplicates address the
    //      same element).
    unsigned int h = ((unsigned int)my * 2654435761u) >> 24;  // 0..255
    bool uniq = false;
    for (;;) {
        int prev = atomicCAS(&s_tab[h], -1, my);
        if (prev == -1) { uniq = true; break; }
        if (prev == my) break;
        h = (h + 1) & 255;
    }

    const float d = yt - yp;
    float v = uniq ? d * d : 0.0f;

    // ---- warp reduce ---------------------------------------------------------
    #pragma unroll
    for (int o = 16; o > 0; o >>= 1)
        v += __shfl_down_sync(0xffffffffu, v, o);

    // ---- tail: ONE packed atomic per warp. The pre-value is simultaneously
    //      the ticket (count bits) and the running total (sum bits) — no
    //      release/acquire pair, no second round trip.
    if ((k & 31) == 0) {
        const unsigned long long contrib =
            (1ULL << 56) |
            (unsigned long long)__float2ll_rn(v * 1073741824.0f);  // * 2^30
        const unsigned long long pre = atomicAdd(&g_pack, contrib);

        if ((pre >> 56) == (unsigned long long)(MB_WARPS_TOTAL - 1)) {
            // I'm the 256th arrival: pre already holds the other 255 sums.
            const long long fixed =
                (long long)((pre + contrib) & 0x00FFFFFFFFFFFFFFULL);
            out[0] = (float)((double)fixed * (1.0 / 1073741824.0));
            g_pack = 0ULL;   // reset for the next graph replay (sole writer;
                             // stream order publishes it before the next launch)
        }
    }
}

// ---------------------------------------------------------------------------
// Launch contract
//   d_in[0] = y_true  (float32, B*N*N)
//   d_in[1] = y_pred  (float32, B*N*N)
//   d_in[2] = rows    (int64 or int32, K)
//   d_in[3] = cols    (int64 or int32, K)
//   d_out   = float32 scalar
// ---------------------------------------------------------------------------
extern "C" void kernel_launch(void* const* d_in, const int* in_sizes, int n_in,
                              void* d_out, int out_size)
{
    const float*        y_true = (const float*)d_in[0];
    const float*        y_pred = (const float*)d_in[1];
    const unsigned int* rows_w = (const unsigned int*)d_in[2];
    const unsigned int* cols_w = (const unsigned int*)d_in[3];
    float*              out    = (float*)d_out;

    masked_loss_fused_kernel<<<MB_B, MB_K>>>(y_true, y_pred, rows_w, cols_w, out);
}